// round 10
// baseline (speedup 1.0000x reference)
#include <cuda_runtime.h>
#include <cuda_bf16.h>
#include <cstdint>

// Problem constants
#define PB 8
#define PT 2048
#define PD 1024
#define PL 4
#define PQD 256
#define NCLS 1000
#define NTOK (PB*PT)           // 16384 rows
#define NEL  ((size_t)NTOK*PD) // 16,777,216

// ---------------- scratch (device globals; no allocation allowed) -------------
__device__ float g_x [NEL];    // activations / residual (fp32)
__device__ float g_r [NEL];    // inter (after FFT + transpose back)
__device__ float g_h [NEL];    // H projection
__device__ float g_qt[NEL];    // Q transposed (b,c,t); reused for inter_t
__device__ float g_rt[NEL];    // R transposed
__device__ __nv_bfloat16 g_xh[NEL];             // bf16 split of g_x (hi)
__device__ __nv_bfloat16 g_xl[NEL];             // bf16 split of g_x (lo)
__device__ __nv_bfloat16 g_wbh[(size_t)12<<20]; // [z][l][n][k] bf16 hi
__device__ __nv_bfloat16 g_wbl[(size_t)12<<20]; // [z][l][n][k] bf16 lo
__device__ float g_partial[PB*16*PD];
__device__ float g_hbuf[PB*PD];

// ---------------- PTX helpers (baseline sm_80-class features only) ------------
__device__ __forceinline__ uint32_t smem_u32(const void *p) {
    uint32_t a;
    asm("{ .reg .u64 t; cvta.to.shared.u64 t, %1; cvt.u32.u64 %0, t; }" : "=r"(a) : "l"(p));
    return a;
}
__device__ __forceinline__ void cp16(uint32_t s, const void *g) {
    asm volatile("cp.async.cg.shared.global [%0], [%1], 16;" :: "r"(s), "l"(g));
}
__device__ __forceinline__ void cp_commit() {
    asm volatile("cp.async.commit_group;" ::: "memory");
}
template <int N> __device__ __forceinline__ void cp_wait() {
    asm volatile("cp.async.wait_group %0;" :: "n"(N) : "memory");
}
__device__ __forceinline__ void ldm_x4(uint32_t *r, uint32_t a) {
    asm volatile("ldmatrix.sync.aligned.m8n8.x4.shared.b16 {%0,%1,%2,%3}, [%4];"
                 : "=r"(r[0]), "=r"(r[1]), "=r"(r[2]), "=r"(r[3]) : "r"(a));
}
__device__ __forceinline__ void mma16816(float *d, const uint32_t *a, const uint32_t *b) {
    asm volatile(
        "mma.sync.aligned.m16n8k16.row.col.f32.bf16.bf16.f32 "
        "{%0,%1,%2,%3}, {%4,%5,%6,%7}, {%8,%9}, {%0,%1,%2,%3};"
        : "+f"(d[0]), "+f"(d[1]), "+f"(d[2]), "+f"(d[3])
        : "r"(a[0]), "r"(a[1]), "r"(a[2]), "r"(a[3]), "r"(b[0]), "r"(b[1]));
}

// GEMM tiling: 256x128 CTA tile, BK=64, 3-stage pipeline
#define STAGE_BYTES 49152      // A 32KB + B 16KB
#define GEMM_SMEM   147456     // 3 stages

// ---------------- block reduce helper ----------------------------------------
__device__ __forceinline__ void block_reduce2(float &s1, float &s2, float *red) {
#pragma unroll
    for (int o = 16; o > 0; o >>= 1) {
        s1 += __shfl_xor_sync(0xffffffffu, s1, o);
        s2 += __shfl_xor_sync(0xffffffffu, s2, o);
    }
    int w = threadIdx.x >> 5, lane = threadIdx.x & 31;
    __syncthreads();
    if (lane == 0) { red[w] = s1; red[32 + w] = s2; }
    __syncthreads();
    int nw = blockDim.x >> 5;
    float a = 0.f, b = 0.f;
    for (int i = 0; i < nw; i++) { a += red[i]; b += red[32 + i]; }
    s1 = a; s2 = b;
}

__device__ __forceinline__ void split_store(size_t idx, float v) {
    __nv_bfloat16 h = __float2bfloat16(v);
    g_xh[idx] = h;
    g_xl[idx] = __float2bfloat16(v - __bfloat162float(h));
}

// ---------------- weight split (all 12 matrices, once per launch) -------------
__global__ __launch_bounds__(256) void convert_w_kernel(const float *__restrict__ Wq,
                                                        const float *__restrict__ Wr,
                                                        const float *__restrict__ Wh) {
    size_t i = (size_t)blockIdx.x * 256 + threadIdx.x;   // 0 .. 4M-1
    int z = blockIdx.y;
    const float *src = (z == 0) ? Wq : (z == 1) ? Wr : Wh;
    float v = src[i];
    __nv_bfloat16 h = __float2bfloat16(v);
    size_t o = ((size_t)z << 22) + i;
    g_wbh[o] = h;
    g_wbl[o] = __float2bfloat16(v - __bfloat162float(h));
}

// ---------------- embedding (+ bf16 split) ------------------------------------
__global__ __launch_bounds__(256) void embed_kernel(const int *__restrict__ tokens,
                                                    const float *__restrict__ embed,
                                                    const float *__restrict__ pos) {
    int row = blockIdx.x;
    int t   = row & (PT - 1);
    int tok = tokens[row];
    int c   = threadIdx.x * 4;
    float4 e = *(const float4 *)(embed + (size_t)tok * PD + c);
    float4 p = *(const float4 *)(pos + (size_t)t * PD + c);
    float4 y = make_float4(e.x + p.x, e.y + p.y, e.z + p.z, e.w + p.w);
    size_t base = (size_t)row * PD + c;
    *(float4 *)(g_x + base) = y;
    split_store(base + 0, y.x); split_store(base + 1, y.y);
    split_store(base + 2, y.z); split_store(base + 3, y.w);
}

// ---------------- mma.sync bf16x3 GEMM (256x128 tile, 3-stage) -----------------
__device__ __forceinline__ void load_chunk_mma(int c, int bm, int bn,
                                               const __nv_bfloat16 *Wh_,
                                               const __nv_bfloat16 *Wl_,
                                               uint32_t buf, int tid) {
    int p  = c >> 4;
    int k0 = (c & 15) << 6;
    const __nv_bfloat16 *A  = (p < 2) ? g_xh : g_xl;
    const __nv_bfloat16 *Bw = (p == 1) ? Wl_ : Wh_;
#pragma unroll
    for (int i = 0; i < 8; i++) {            // A: 256 rows x 128B = 32KB
        int idx = tid + (i << 8);
        int r = idx >> 3, cc = idx & 7;
        const void *g = A + (size_t)(bm + r) * PD + k0 + cc * 8;
        cp16(buf + r * 128 + ((cc ^ (r & 7)) << 4), g);
    }
#pragma unroll
    for (int i = 0; i < 4; i++) {            // B: 128 rows x 128B = 16KB
        int idx = tid + (i << 8);
        int r = idx >> 3, cc = idx & 7;
        const void *g = Bw + (size_t)(bn + r) * PD + k0 + cc * 8;
        cp16(buf + 32768 + r * 128 + ((cc ^ (r & 7)) << 4), g);
    }
    cp_commit();
}

__global__ __launch_bounds__(256, 1) void gemm_mma_kernel(int l,
                                                          const float *__restrict__ bq,
                                                          const float *__restrict__ br,
                                                          const float *__restrict__ bh) {
    extern __shared__ char smem[];
    const int tid  = threadIdx.x;
    const int lane = tid & 31;
    const int wid  = tid >> 5;
    const int wm   = wid & 3;        // 4 warps in M
    const int wn   = wid >> 2;       // 2 warps in N
    const int z    = blockIdx.z;
    const int bn   = blockIdx.x * 128;
    const int bm   = blockIdx.y * 256;
    const uint32_t sb = smem_u32(smem);

    const size_t woff = ((size_t)(z * PL + l)) << 20;
    const __nv_bfloat16 *Wh_ = g_wbh + woff;
    const __nv_bfloat16 *Wl_ = g_wbl + woff;

    float acc[4][8][4];
#pragma unroll
    for (int i = 0; i < 4; i++)
#pragma unroll
        for (int j = 0; j < 8; j++)
#pragma unroll
            for (int k = 0; k < 4; k++) acc[i][j][k] = 0.f;

    const int aRow  = wm * 64 + (lane & 15);
    const int aHalf = lane >> 4;
    const int aSw   = aRow & 7;
    const int bRow  = wn * 64 + (lane & 7) + ((lane >> 4) << 3);
    const int bHalf = (lane >> 3) & 1;
    const int bSw   = bRow & 7;

    load_chunk_mma(0, bm, bn, Wh_, Wl_, sb, tid);
    load_chunk_mma(1, bm, bn, Wh_, Wl_, sb + STAGE_BYTES, tid);

#pragma unroll 1
    for (int c = 0; c < 48; c++) {
        const uint32_t Ab = sb + (uint32_t)(c % 3) * STAGE_BYTES;
        const uint32_t Bb = Ab + 32768;
        if (c + 2 < 48) {
            load_chunk_mma(c + 2, bm, bn, Wh_, Wl_,
                           sb + (uint32_t)((c + 2) % 3) * STAGE_BYTES, tid);
            cp_wait<2>();
        } else if (c + 1 < 48) {
            cp_wait<1>();
        } else {
            cp_wait<0>();
        }
        __syncthreads();

#pragma unroll
        for (int ks = 0; ks < 4; ks++) {
            uint32_t a[4][4];
#pragma unroll
            for (int im = 0; im < 4; im++) {
                uint32_t addr = Ab + (uint32_t)(aRow + im * 16) * 128
                              + (uint32_t)(((ks * 2 + aHalf) ^ aSw) << 4);
                ldm_x4(a[im], addr);
            }
            uint32_t b[4][4];
#pragma unroll
            for (int np = 0; np < 4; np++) {
                uint32_t addr = Bb + (uint32_t)(bRow + np * 16) * 128
                              + (uint32_t)(((ks * 2 + bHalf) ^ bSw) << 4);
                ldm_x4(b[np], addr);
            }
#pragma unroll
            for (int im = 0; im < 4; im++)
#pragma unroll
                for (int jn = 0; jn < 8; jn++)
                    mma16816(acc[im][jn], a[im], &b[jn >> 1][(jn & 1) << 1]);
        }
        __syncthreads();
    }

    const float *bias = (z == 0) ? bq : (z == 1) ? br : bh;
    if (z == 2) {
#pragma unroll
        for (int im = 0; im < 4; im++) {
            int r0 = bm + wm * 64 + im * 16 + (lane >> 2);
#pragma unroll
            for (int jn = 0; jn < 8; jn++) {
                int c0 = bn + wn * 64 + jn * 8 + (lane & 3) * 2;
                float b0 = __ldg(bias + c0), b1 = __ldg(bias + c0 + 1);
                float2 v0 = make_float2(acc[im][jn][0] + b0, acc[im][jn][1] + b1);
                float2 v1 = make_float2(acc[im][jn][2] + b0, acc[im][jn][3] + b1);
                *(float2 *)(g_h + (size_t)r0 * PD + c0)       = v0;
                *(float2 *)(g_h + (size_t)(r0 + 8) * PD + c0) = v1;
            }
        }
    } else {
        float *outp = (z == 0) ? g_qt : g_rt;
#pragma unroll
        for (int im = 0; im < 4; im++) {
            int m0 = bm + wm * 64 + im * 16 + (lane >> 2);
            int b_  = m0 >> 11;
            int t0  = m0 & (PT - 1);
            float *ob = outp + ((size_t)b_ << 21);
#pragma unroll
            for (int jn = 0; jn < 8; jn++) {
                int c0 = bn + wn * 64 + jn * 8 + (lane & 3) * 2;
                float b0 = __ldg(bias + c0), b1 = __ldg(bias + c0 + 1);
                ob[(size_t)c0 * PT + t0]           = acc[im][jn][0] + b0;
                ob[(size_t)(c0 + 1) * PT + t0]     = acc[im][jn][1] + b1;
                ob[(size_t)c0 * PT + t0 + 8]       = acc[im][jn][2] + b0;
                ob[(size_t)(c0 + 1) * PT + t0 + 8] = acc[im][jn][3] + b1;
            }
        }
    }
}

// ---------------- transpose inter_t (b,c,t) -> (b,t,c) ------------------------
__global__ __launch_bounds__(256) void transpose_back_kernel() {
    __shared__ float tile[32][33];
    int b  = blockIdx.z;
    int j0 = blockIdx.x * 32;   // input col (t)
    int i0 = blockIdx.y * 32;   // input row (c)
    const float *ib = g_qt + (size_t)b * PD * PT;
    float *ob = g_r + (size_t)b * PD * PT;
#pragma unroll
    for (int r = threadIdx.y; r < 32; r += 8)
        tile[r][threadIdx.x] = ib[(size_t)(i0 + r) * PT + j0 + threadIdx.x];
    __syncthreads();
#pragma unroll
    for (int r = threadIdx.y; r < 32; r += 8)
        ob[(size_t)(j0 + r) * PD + i0 + threadIdx.x] = tile[threadIdx.x][r];
}

// ---------------- radix-8 Stockham FFT (2048-pt, 256 threads) -----------------
#define FPAD(i) ((i) + ((i) >> 3))

__device__ __forceinline__ float2 cmul(float2 a, float2 b) {
    return make_float2(a.x * b.x - a.y * b.y, a.x * b.y + a.y * b.x);
}
__device__ __forceinline__ float2 cadd(float2 a, float2 b) { return make_float2(a.x + b.x, a.y + b.y); }
__device__ __forceinline__ float2 csub(float2 a, float2 b) { return make_float2(a.x - b.x, a.y - b.y); }

__device__ __forceinline__ void dft8(float2 *v) {
    const float C = 0.70710678118654752f;
    float2 a0 = cadd(v[0], v[4]), a4 = csub(v[0], v[4]);
    float2 a1 = cadd(v[1], v[5]), a5 = csub(v[1], v[5]);
    float2 a2 = cadd(v[2], v[6]), a6 = csub(v[2], v[6]);
    float2 a3 = cadd(v[3], v[7]), a7 = csub(v[3], v[7]);
    a5 = make_float2(C * (a5.x + a5.y), C * (a5.y - a5.x));
    a6 = make_float2(a6.y, -a6.x);
    a7 = make_float2(C * (a7.y - a7.x), -C * (a7.x + a7.y));
    float2 b0 = cadd(a0, a2), b2 = csub(a0, a2);
    float2 b1 = cadd(a1, a3), b3 = csub(a1, a3);
    b3 = make_float2(b3.y, -b3.x);
    float2 b4 = cadd(a4, a6), b6 = csub(a4, a6);
    float2 b5 = cadd(a5, a7), b7 = csub(a5, a7);
    b7 = make_float2(b7.y, -b7.x);
    v[0] = cadd(b0, b1);  v[4] = csub(b0, b1);
    v[2] = cadd(b2, b3);  v[6] = csub(b2, b3);
    v[1] = cadd(b4, b5);  v[5] = csub(b4, b5);
    v[3] = cadd(b6, b7);  v[7] = csub(b6, b7);
}

template <int NS>
__device__ __forceinline__ void step8s(const float2 *in, float2 *out, int j) {
    float2 v[8];
#pragma unroll
    for (int r = 0; r < 8; r++) v[r] = in[FPAD(j + (r << 8))];
    if (NS > 1) {
        const int m = j & (NS - 1);
        float2 w1;
        __sincosf((float)m * (-6.283185307179586f / (NS * 8)), &w1.y, &w1.x);
        float2 w = w1;
#pragma unroll
        for (int r = 1; r < 8; r++) { v[r] = cmul(v[r], w); w = cmul(w, w1); }
    }
    dft8(v);
    const int m2 = j & (NS - 1);
    const int base = ((j - m2) << 3) + m2;
#pragma unroll
    for (int r = 0; r < 8; r++) out[FPAD(base + r * NS)] = v[r];
}

__device__ __forceinline__ void step4_512(const float2 *in, float2 *out, int j) {
    float2 v[4];
#pragma unroll
    for (int r = 0; r < 4; r++) v[r] = in[FPAD(j + (r << 9))];
    float2 w1;
    __sincosf((float)j * (-6.283185307179586f / 2048.f), &w1.y, &w1.x);
    v[1] = cmul(v[1], w1);
    float2 w2 = cmul(w1, w1);
    v[2] = cmul(v[2], w2);
    v[3] = cmul(v[3], cmul(w2, w1));
    float2 a0 = cadd(v[0], v[2]), a2 = csub(v[0], v[2]);
    float2 a1 = cadd(v[1], v[3]), a3 = csub(v[1], v[3]);
    a3 = make_float2(a3.y, -a3.x);
    out[FPAD(j)]        = cadd(a0, a1);
    out[FPAD(j + 512)]  = cadd(a2, a3);
    out[FPAD(j + 1024)] = csub(a0, a1);
    out[FPAD(j + 1536)] = csub(a2, a3);
}

__device__ __forceinline__ void fft2048s(float2 *bA, float2 *bB, int tid) {
    step8s<1>(bA, bB, tid);   __syncthreads();
    step8s<8>(bB, bA, tid);   __syncthreads();
    step8s<64>(bA, bB, tid);  __syncthreads();
    step4_512(bB, bA, tid);
    step4_512(bB, bA, tid + 256);
    __syncthreads();
}

__device__ __forceinline__ void spectral_H(const float2 *bA, float alpha, float2 *H, int tid) {
#pragma unroll
    for (int i = 0; i < 8; i++) {
        int k  = tid + (i << 8);
        int km = (2048 - k) & 2047;
        float2 Z  = bA[FPAD(k)];
        float2 Zm = bA[FPAD(km)];
        float qr = 0.5f * (Z.x + Zm.x);
        float qi = 0.5f * (Z.y - Zm.y);
        float rr = 0.5f * (Z.y + Zm.y);
        float ri = 0.5f * (Zm.x - Z.x);
        float mq = sqrtf(qr * qr + qi * qi);
        float mr = sqrtf(rr * rr + ri * ri);
        float pq = alpha * atanf(__logf(mq + 1e-8f));
        float pr = alpha * atanf(__logf(mr + 1e-8f));
        float cw = __cosf(pq - pr);
        H[i] = make_float2((qr * rr + qi * ri) * cw, (qi * rr - qr * ri) * cw);
    }
}

__global__ __launch_bounds__(256) void fft_cross_kernel(const float *__restrict__ alpha_l) {
    __shared__ float2 bA[2304];
    __shared__ float2 bB[2304];
    const int tid = threadIdx.x;
    const int c0  = blockIdx.x * 2;
    const int c1  = c0 + 1;
    const int b   = blockIdx.y;
    const float al0 = alpha_l[c0 & (PQD - 1)];
    const float al1 = alpha_l[c1 & (PQD - 1)];
    const size_t r0 = ((size_t)(b * PD + c0)) * PT;
    const size_t r1 = ((size_t)(b * PD + c1)) * PT;

    float2 H1[8], H2[8];

#pragma unroll
    for (int i = 0; i < 8; i++) {
        int t = tid + (i << 8);
        bA[FPAD(t)] = make_float2(g_qt[r0 + t], g_rt[r0 + t]);
    }
    __syncthreads();
    fft2048s(bA, bB, tid);
    spectral_H(bA, al0, H1, tid);
    __syncthreads();

#pragma unroll
    for (int i = 0; i < 8; i++) {
        int t = tid + (i << 8);
        bA[FPAD(t)] = make_float2(g_qt[r1 + t], g_rt[r1 + t]);
    }
    __syncthreads();
    fft2048s(bA, bB, tid);
    spectral_H(bA, al1, H2, tid);
    __syncthreads();

#pragma unroll
    for (int i = 0; i < 8; i++) {
        int k = tid + (i << 8);
        bA[FPAD(k)] = make_float2(H1[i].x - H2[i].y, -(H1[i].y + H2[i].x));
    }
    __syncthreads();
    fft2048s(bA, bB, tid);
    const float s = 1.0f / 2048.0f;
#pragma unroll
    for (int i = 0; i < 8; i++) {
        int t = tid + (i << 8);
        float2 F = bA[FPAD(t)];
        g_qt[r0 + t] = F.x * s;
        g_qt[r1 + t] = -F.y * s;
    }
}

// ---------------- fused hamilton + LN + gate + rot + residual + LN ------------
__global__ __launch_bounds__(256) void ham_ln_kernel(const float *__restrict__ spw,
                                                     const float *__restrict__ spb,
                                                     const float *__restrict__ gate,
                                                     const float *__restrict__ rot,
                                                     const float *__restrict__ ow,
                                                     const float *__restrict__ ob) {
    __shared__ float red[64];
    const int row = blockIdx.x;
    const size_t base = (size_t)row * PD;
    const int d = threadIdx.x;

    float i0 = g_r[base + d],       i1 = g_r[base + 256 + d];
    float i2 = g_r[base + 512 + d], i3 = g_r[base + 768 + d];
    float h0 = g_h[base + d],       h1 = g_h[base + 256 + d];
    float h2 = g_h[base + 512 + d], h3 = g_h[base + 768 + d];

    float qw = i0 * h0 - i1 * h1 - i2 * h2 - i3 * h3;
    float qx = i0 * h1 + i1 * h0 + i2 * h3 - i3 * h2;
    float qy = i0 * h2 - i1 * h3 + i2 * h0 + i3 * h1;
    float qz = i0 * h3 + i1 * h2 - i2 * h1 + i3 * h0;

    float s1 = qw + qx + qy + qz;
    float s2 = qw * qw + qx * qx + qy * qy + qz * qz;
    block_reduce2(s1, s2, red);
    float mean = s1 * (1.f / 1024.f);
    float var  = s2 * (1.f / 1024.f) - mean * mean;
    float inv  = rsqrtf(var + 1e-5f);
    float t0 = (qw - mean) * inv * spw[d]       + spb[d];
    float t1 = (qx - mean) * inv * spw[256 + d] + spb[256 + d];
    float t2 = (qy - mean) * inv * spw[512 + d] + spb[512 + d];
    float t3 = (qz - mean) * inv * spw[768 + d] + spb[768 + d];

    float g = gate[d];
    float f0 = t0 * g, f1 = t1 * g, f2 = t2 * g, f3 = t3 * g;
    float x0 = rot[0]  * f0 + rot[1]  * f1 + rot[2]  * f2 + rot[3]  * f3;
    float x1 = rot[4]  * f0 + rot[5]  * f1 + rot[6]  * f2 + rot[7]  * f3;
    float x2 = rot[8]  * f0 + rot[9]  * f1 + rot[10] * f2 + rot[11] * f3;
    float x3 = rot[12] * f0 + rot[13] * f1 + rot[14] * f2 + rot[15] * f3;

    x0 += g_x[base + d];
    x1 += g_x[base + 256 + d];
    x2 += g_x[base + 512 + d];
    x3 += g_x[base + 768 + d];
    s1 = x0 + x1 + x2 + x3;
    s2 = x0 * x0 + x1 * x1 + x2 * x2 + x3 * x3;
    block_reduce2(s1, s2, red);
    mean = s1 * (1.f / 1024.f);
    var  = s2 * (1.f / 1024.f) - mean * mean;
    inv  = rsqrtf(var + 1e-5f);
    float y0 = (x0 - mean) * inv * ow[d]       + ob[d];
    float y1 = (x1 - mean) * inv * ow[256 + d] + ob[256 + d];
    float y2 = (x2 - mean) * inv * ow[512 + d] + ob[512 + d];
    float y3 = (x3 - mean) * inv * ow[768 + d] + ob[768 + d];
    g_x[base + d]       = y0;
    g_x[base + 256 + d] = y1;
    g_x[base + 512 + d] = y2;
    g_x[base + 768 + d] = y3;
    split_store(base + d,       y0);
    split_store(base + 256 + d, y1);
    split_store(base + 512 + d, y2);
    split_store(base + 768 + d, y3);
}

// ---------------- pooling + cls LN -------------------------------------------
__global__ __launch_bounds__(1024) void pool_partial_kernel() {
    int b = blockIdx.y, ch = blockIdx.x, c = threadIdx.x;
    float s = 0.f;
    size_t base = ((size_t)b * PT + ch * 128) * PD + c;
    for (int t = 0; t < 128; t++) s += g_x[base + (size_t)t * PD];
    g_partial[(b * 16 + ch) * PD + c] = s;
}

__global__ __launch_bounds__(1024) void pool_finish_kernel(const float *__restrict__ clw,
                                                           const float *__restrict__ clb) {
    __shared__ float red[64];
    int b = blockIdx.x, c = threadIdx.x;
    float s = 0.f;
    for (int ch = 0; ch < 16; ch++) s += g_partial[(b * 16 + ch) * PD + c];
    float v = s * (1.f / (float)PT);
    float s1 = v, s2 = v * v;
    block_reduce2(s1, s2, red);
    float mean = s1 * (1.f / 1024.f);
    float var  = s2 * (1.f / 1024.f) - mean * mean;
    float inv  = rsqrtf(var + 1e-5f);
    g_hbuf[b * PD + c] = (v - mean) * inv * clw[c] + clb[c];
}

__global__ __launch_bounds__(128) void cls_kernel(const float *__restrict__ cW,
                                                  const float *__restrict__ cb,
                                                  float *__restrict__ out) {
    int n = blockIdx.x, b = blockIdx.y, tid = threadIdx.x;
    float s = 0.f;
    for (int c = tid; c < PD; c += 128) s += g_hbuf[b * PD + c] * cW[(size_t)n * PD + c];
#pragma unroll
    for (int o = 16; o > 0; o >>= 1) s += __shfl_xor_sync(0xffffffffu, s, o);
    __shared__ float sr[4];
    if ((tid & 31) == 0) sr[tid >> 5] = s;
    __syncthreads();
    if (tid == 0) out[b * NCLS + n] = sr[0] + sr[1] + sr[2] + sr[3] + cb[n];
}

// ---------------- host ---------------------------------------------------------
extern "C" void kernel_launch(void *const *d_in, const int *in_sizes, int n_in,
                              void *d_out, int out_size) {
    (void)in_sizes; (void)n_in; (void)out_size;
    const int   *tokens = (const int *)d_in[0];
    const float *embed  = (const float *)d_in[1];
    const float *pos    = (const float *)d_in[2];
    const float *Wq     = (const float *)d_in[3];
    const float *bq     = (const float *)d_in[4];
    const float *Wr     = (const float *)d_in[5];
    const float *br     = (const float *)d_in[6];
    const float *Wh     = (const float *)d_in[7];
    const float *bh     = (const float *)d_in[8];
    const float *alpha  = (const float *)d_in[9];
    const float *spw    = (const float *)d_in[10];
    const float *spb    = (const float *)d_in[11];
    const float *gate   = (const float *)d_in[12];
    const float *rot    = (const float *)d_in[13];
    const float *ow     = (const float *)d_in[14];
    const float *ob     = (const float *)d_in[15];
    const float *clw    = (const float *)d_in[16];
    const float *clb    = (const float *)d_in[17];
    const float *cW     = (const float *)d_in[18];
    const float *cb     = (const float *)d_in[19];
    float *out = (float *)d_out;

    cudaFuncSetAttribute(gemm_mma_kernel, cudaFuncAttributeMaxDynamicSharedMemorySize, GEMM_SMEM);

    convert_w_kernel<<<dim3(16384, 3), 256>>>(Wq, Wr, Wh);
    embed_kernel<<<NTOK, 256>>>(tokens, embed, pos);

    for (int l = 0; l < PL; l++) {
        gemm_mma_kernel<<<dim3(8, 64, 3), 256, GEMM_SMEM>>>(l, bq + l * PD, br + l * PD, bh + l * PD);
        fft_cross_kernel<<<dim3(PD / 2, PB), 256>>>(alpha + l * PQD);
        transpose_back_kernel<<<dim3(64, 32, PB), dim3(32, 8)>>>();
        ham_ln_kernel<<<NTOK, 256>>>(spw + l * PD, spb + l * PD,
                                     gate + l * PQD, rot + l * 16,
                                     ow + l * PD, ob + l * PD);
    }

    pool_partial_kernel<<<dim3(16, PB), 1024>>>();
    pool_finish_kernel<<<PB, 1024>>>(clw, clb);
    cls_kernel<<<dim3(NCLS, PB), 128>>>(cW, cb, out);
}

// round 11
// speedup vs baseline: 1.1222x; 1.1222x over previous
#include <cuda_runtime.h>
#include <cuda_bf16.h>
#include <cstdint>

// Problem constants
#define PB 8
#define PT 2048
#define PD 1024
#define PL 4
#define PQD 256
#define NCLS 1000
#define NTOK (PB*PT)           // 16384 rows
#define NEL  ((size_t)NTOK*PD) // 16,777,216

// ---------------- scratch (device globals; no allocation allowed) -------------
__device__ float g_x [NEL];    // activations / residual (fp32)
__device__ float g_r [NEL];    // inter (after FFT + transpose back)
__device__ float g_h [NEL];    // H projection
__device__ float g_qt[NEL];    // Q transposed (b,c,t); reused for inter_t
__device__ float g_rt[NEL];    // R transposed
__device__ __nv_bfloat16 g_xh[NEL];             // bf16 split of g_x (hi)
__device__ __nv_bfloat16 g_xl[NEL];             // bf16 split of g_x (lo)
__device__ __nv_bfloat16 g_wbh[(size_t)12<<20]; // [z][l][n][k] bf16 hi
__device__ __nv_bfloat16 g_wbl[(size_t)12<<20]; // [z][l][n][k] bf16 lo
__device__ float g_partial[PB*16*PD];
__device__ float g_hbuf[PB*PD];

// ---------------- PTX helpers (baseline sm_80-class features only) ------------
__device__ __forceinline__ uint32_t smem_u32(const void *p) {
    uint32_t a;
    asm("{ .reg .u64 t; cvta.to.shared.u64 t, %1; cvt.u32.u64 %0, t; }" : "=r"(a) : "l"(p));
    return a;
}
__device__ __forceinline__ void cp16(uint32_t s, const void *g) {
    asm volatile("cp.async.cg.shared.global [%0], [%1], 16;" :: "r"(s), "l"(g));
}
__device__ __forceinline__ void cp_commit() {
    asm volatile("cp.async.commit_group;" ::: "memory");
}
template <int N> __device__ __forceinline__ void cp_wait() {
    asm volatile("cp.async.wait_group %0;" :: "n"(N) : "memory");
}
__device__ __forceinline__ void ldm_x4(uint32_t *r, uint32_t a) {
    asm volatile("ldmatrix.sync.aligned.m8n8.x4.shared.b16 {%0,%1,%2,%3}, [%4];"
                 : "=r"(r[0]), "=r"(r[1]), "=r"(r[2]), "=r"(r[3]) : "r"(a));
}
__device__ __forceinline__ void mma16816(float *d, const uint32_t *a, const uint32_t *b) {
    asm volatile(
        "mma.sync.aligned.m16n8k16.row.col.f32.bf16.bf16.f32 "
        "{%0,%1,%2,%3}, {%4,%5,%6,%7}, {%8,%9}, {%0,%1,%2,%3};"
        : "+f"(d[0]), "+f"(d[1]), "+f"(d[2]), "+f"(d[3])
        : "r"(a[0]), "r"(a[1]), "r"(a[2]), "r"(a[3]), "r"(b[0]), "r"(b[1]));
}

// dynamic smem: 2 buffers x (A 16KB + B 16KB) = 64KB  (R7 proven config)
#define BUF_BYTES 32768
#define SMEM_TOTAL 65536

// ---------------- block reduce helper ----------------------------------------
__device__ __forceinline__ void block_reduce2(float &s1, float &s2, float *red) {
#pragma unroll
    for (int o = 16; o > 0; o >>= 1) {
        s1 += __shfl_xor_sync(0xffffffffu, s1, o);
        s2 += __shfl_xor_sync(0xffffffffu, s2, o);
    }
    int w = threadIdx.x >> 5, lane = threadIdx.x & 31;
    __syncthreads();
    if (lane == 0) { red[w] = s1; red[32 + w] = s2; }
    __syncthreads();
    int nw = blockDim.x >> 5;
    float a = 0.f, b = 0.f;
    for (int i = 0; i < nw; i++) { a += red[i]; b += red[32 + i]; }
    s1 = a; s2 = b;
}

__device__ __forceinline__ void split_store(size_t idx, float v) {
    __nv_bfloat16 h = __float2bfloat16(v);
    g_xh[idx] = h;
    g_xl[idx] = __float2bfloat16(v - __bfloat162float(h));
}

// ---------------- weight split (all 12 matrices, once per launch) -------------
__global__ __launch_bounds__(256) void convert_w_kernel(const float *__restrict__ Wq,
                                                        const float *__restrict__ Wr,
                                                        const float *__restrict__ Wh) {
    size_t i = (size_t)blockIdx.x * 256 + threadIdx.x;   // 0 .. 4M-1
    int z = blockIdx.y;
    const float *src = (z == 0) ? Wq : (z == 1) ? Wr : Wh;
    float v = src[i];
    __nv_bfloat16 h = __float2bfloat16(v);
    size_t o = ((size_t)z << 22) + i;
    g_wbh[o] = h;
    g_wbl[o] = __float2bfloat16(v - __bfloat162float(h));
}

// ---------------- embedding (+ bf16 split) ------------------------------------
__global__ __launch_bounds__(256) void embed_kernel(const int *__restrict__ tokens,
                                                    const float *__restrict__ embed,
                                                    const float *__restrict__ pos) {
    int row = blockIdx.x;
    int t   = row & (PT - 1);
    int tok = tokens[row];
    int c   = threadIdx.x * 4;
    float4 e = *(const float4 *)(embed + (size_t)tok * PD + c);
    float4 p = *(const float4 *)(pos + (size_t)t * PD + c);
    float4 y = make_float4(e.x + p.x, e.y + p.y, e.z + p.z, e.w + p.w);
    size_t base = (size_t)row * PD + c;
    *(float4 *)(g_x + base) = y;
    split_store(base + 0, y.x); split_store(base + 1, y.y);
    split_store(base + 2, y.z); split_store(base + 3, y.w);
}

// ---------------- mma.sync bf16x3 GEMM (128x128 tile, 2-stage; R7 config) -----
__device__ __forceinline__ void load_chunk_mma(int c, int bm, int bn,
                                               const __nv_bfloat16 *Wh_,
                                               const __nv_bfloat16 *Wl_,
                                               uint32_t buf, int tid) {
    int p  = c >> 4;
    int k0 = (c & 15) << 6;
    const __nv_bfloat16 *A  = (p < 2) ? g_xh : g_xl;
    const __nv_bfloat16 *Bw = (p == 1) ? Wl_ : Wh_;
#pragma unroll
    for (int i = 0; i < 4; i++) {            // A: 128 rows x 128B = 16KB
        int idx = tid + (i << 8);
        int r = idx >> 3, cc = idx & 7;
        const void *g = A + (size_t)(bm + r) * PD + k0 + cc * 8;
        cp16(buf + r * 128 + ((cc ^ (r & 7)) << 4), g);
    }
#pragma unroll
    for (int i = 0; i < 4; i++) {            // B: 128 rows x 128B = 16KB
        int idx = tid + (i << 8);
        int r = idx >> 3, cc = idx & 7;
        const void *g = Bw + (size_t)(bn + r) * PD + k0 + cc * 8;
        cp16(buf + 16384 + r * 128 + ((cc ^ (r & 7)) << 4), g);
    }
    cp_commit();
}

__global__ __launch_bounds__(256) void gemm_mma_kernel(int l, int zbase,
                                                       const float *__restrict__ bq,
                                                       const float *__restrict__ br,
                                                       const float *__restrict__ bh) {
    extern __shared__ char smem[];
    const int tid  = threadIdx.x;
    const int lane = tid & 31;
    const int wid  = tid >> 5;
    const int wm   = wid & 1;        // 2 warps in M
    const int wn   = wid >> 1;       // 4 warps in N
    const int z    = zbase + blockIdx.z;
    const int bn   = blockIdx.x * 128;
    const int bm   = blockIdx.y * 128;
    const uint32_t sb = smem_u32(smem);

    const size_t woff = ((size_t)(z * PL + l)) << 20;
    const __nv_bfloat16 *Wh_ = g_wbh + woff;
    const __nv_bfloat16 *Wl_ = g_wbl + woff;

    float acc[4][4][4];
#pragma unroll
    for (int i = 0; i < 4; i++)
#pragma unroll
        for (int j = 0; j < 4; j++)
#pragma unroll
            for (int k = 0; k < 4; k++) acc[i][j][k] = 0.f;

    const int aRow  = wm * 64 + (lane & 15);
    const int aHalf = lane >> 4;
    const int aSw   = aRow & 7;
    const int bRow  = wn * 32 + (lane & 7) + ((lane >> 4) << 3);
    const int bHalf = (lane >> 3) & 1;
    const int bSw   = bRow & 7;

    load_chunk_mma(0, bm, bn, Wh_, Wl_, sb, tid);

#pragma unroll 1
    for (int c = 0; c < 48; c++) {
        const uint32_t Ab = sb + (uint32_t)(c & 1) * BUF_BYTES;
        const uint32_t Bb = Ab + 16384;
        if (c + 1 < 48) {
            load_chunk_mma(c + 1, bm, bn, Wh_, Wl_,
                           sb + (uint32_t)((c + 1) & 1) * BUF_BYTES, tid);
            cp_wait<1>();
        } else {
            cp_wait<0>();
        }
        __syncthreads();

#pragma unroll
        for (int ks = 0; ks < 4; ks++) {
            uint32_t a[4][4];
#pragma unroll
            for (int im = 0; im < 4; im++) {
                uint32_t addr = Ab + (uint32_t)(aRow + im * 16) * 128
                              + (uint32_t)(((ks * 2 + aHalf) ^ aSw) << 4);
                ldm_x4(a[im], addr);
            }
            uint32_t b[2][4];
#pragma unroll
            for (int np = 0; np < 2; np++) {
                uint32_t addr = Bb + (uint32_t)(bRow + np * 16) * 128
                              + (uint32_t)(((ks * 2 + bHalf) ^ bSw) << 4);
                ldm_x4(b[np], addr);
            }
#pragma unroll
            for (int im = 0; im < 4; im++)
#pragma unroll
                for (int jn = 0; jn < 4; jn++)
                    mma16816(acc[im][jn], a[im], &b[jn >> 1][(jn & 1) << 1]);
        }
        __syncthreads();
    }

    const float *bias = (z == 0) ? bq : (z == 1) ? br : bh;
    if (z == 2) {
#pragma unroll
        for (int im = 0; im < 4; im++) {
            int r0 = bm + wm * 64 + im * 16 + (lane >> 2);
#pragma unroll
            for (int jn = 0; jn < 4; jn++) {
                int c0 = bn + wn * 32 + jn * 8 + (lane & 3) * 2;
                float b0 = __ldg(bias + c0), b1 = __ldg(bias + c0 + 1);
                float2 v0 = make_float2(acc[im][jn][0] + b0, acc[im][jn][1] + b1);
                float2 v1 = make_float2(acc[im][jn][2] + b0, acc[im][jn][3] + b1);
                *(float2 *)(g_h + (size_t)r0 * PD + c0)       = v0;
                *(float2 *)(g_h + (size_t)(r0 + 8) * PD + c0) = v1;
            }
        }
    } else {
        float *outp = (z == 0) ? g_qt : g_rt;
#pragma unroll
        for (int im = 0; im < 4; im++) {
            int m0 = bm + wm * 64 + im * 16 + (lane >> 2);
            int b_  = m0 >> 11;
            int t0  = m0 & (PT - 1);
            float *ob = outp + ((size_t)b_ << 21);
#pragma unroll
            for (int jn = 0; jn < 4; jn++) {
                int c0 = bn + wn * 32 + jn * 8 + (lane & 3) * 2;
                float b0 = __ldg(bias + c0), b1 = __ldg(bias + c0 + 1);
                ob[(size_t)c0 * PT + t0]           = acc[im][jn][0] + b0;
                ob[(size_t)(c0 + 1) * PT + t0]     = acc[im][jn][1] + b1;
                ob[(size_t)c0 * PT + t0 + 8]       = acc[im][jn][2] + b0;
                ob[(size_t)(c0 + 1) * PT + t0 + 8] = acc[im][jn][3] + b1;
            }
        }
    }
}

// ---------------- transpose inter_t (b,c,t) -> (b,t,c) ------------------------
__global__ __launch_bounds__(256) void transpose_back_kernel() {
    __shared__ float tile[32][33];
    int b  = blockIdx.z;
    int j0 = blockIdx.x * 32;   // input col (t)
    int i0 = blockIdx.y * 32;   // input row (c)
    const float *ib = g_qt + (size_t)b * PD * PT;
    float *ob = g_r + (size_t)b * PD * PT;
#pragma unroll
    for (int r = threadIdx.y; r < 32; r += 8)
        tile[r][threadIdx.x] = ib[(size_t)(i0 + r) * PT + j0 + threadIdx.x];
    __syncthreads();
#pragma unroll
    for (int r = threadIdx.y; r < 32; r += 8)
        ob[(size_t)(j0 + r) * PD + i0 + threadIdx.x] = tile[threadIdx.x][r];
}

// ---------------- radix-8 Stockham FFT (2048-pt, 256 threads) -----------------
#define FPAD(i) ((i) + ((i) >> 3))

__device__ __forceinline__ float2 cmul(float2 a, float2 b) {
    return make_float2(a.x * b.x - a.y * b.y, a.x * b.y + a.y * b.x);
}
__device__ __forceinline__ float2 cadd(float2 a, float2 b) { return make_float2(a.x + b.x, a.y + b.y); }
__device__ __forceinline__ float2 csub(float2 a, float2 b) { return make_float2(a.x - b.x, a.y - b.y); }

__device__ __forceinline__ void dft8(float2 *v) {
    const float C = 0.70710678118654752f;
    float2 a0 = cadd(v[0], v[4]), a4 = csub(v[0], v[4]);
    float2 a1 = cadd(v[1], v[5]), a5 = csub(v[1], v[5]);
    float2 a2 = cadd(v[2], v[6]), a6 = csub(v[2], v[6]);
    float2 a3 = cadd(v[3], v[7]), a7 = csub(v[3], v[7]);
    a5 = make_float2(C * (a5.x + a5.y), C * (a5.y - a5.x));
    a6 = make_float2(a6.y, -a6.x);
    a7 = make_float2(C * (a7.y - a7.x), -C * (a7.x + a7.y));
    float2 b0 = cadd(a0, a2), b2 = csub(a0, a2);
    float2 b1 = cadd(a1, a3), b3 = csub(a1, a3);
    b3 = make_float2(b3.y, -b3.x);
    float2 b4 = cadd(a4, a6), b6 = csub(a4, a6);
    float2 b5 = cadd(a5, a7), b7 = csub(a5, a7);
    b7 = make_float2(b7.y, -b7.x);
    v[0] = cadd(b0, b1);  v[4] = csub(b0, b1);
    v[2] = cadd(b2, b3);  v[6] = csub(b2, b3);
    v[1] = cadd(b4, b5);  v[5] = csub(b4, b5);
    v[3] = cadd(b6, b7);  v[7] = csub(b6, b7);
}

template <int NS>
__device__ __forceinline__ void step8s(const float2 *in, float2 *out, int j) {
    float2 v[8];
#pragma unroll
    for (int r = 0; r < 8; r++) v[r] = in[FPAD(j + (r << 8))];
    if (NS > 1) {
        const int m = j & (NS - 1);
        float2 w1;
        __sincosf((float)m * (-6.283185307179586f / (NS * 8)), &w1.y, &w1.x);
        float2 w = w1;
#pragma unroll
        for (int r = 1; r < 8; r++) { v[r] = cmul(v[r], w); w = cmul(w, w1); }
    }
    dft8(v);
    const int m2 = j & (NS - 1);
    const int base = ((j - m2) << 3) + m2;
#pragma unroll
    for (int r = 0; r < 8; r++) out[FPAD(base + r * NS)] = v[r];
}

__device__ __forceinline__ void step4_512(const float2 *in, float2 *out, int j) {
    float2 v[4];
#pragma unroll
    for (int r = 0; r < 4; r++) v[r] = in[FPAD(j + (r << 9))];
    float2 w1;
    __sincosf((float)j * (-6.283185307179586f / 2048.f), &w1.y, &w1.x);
    v[1] = cmul(v[1], w1);
    float2 w2 = cmul(w1, w1);
    v[2] = cmul(v[2], w2);
    v[3] = cmul(v[3], cmul(w2, w1));
    float2 a0 = cadd(v[0], v[2]), a2 = csub(v[0], v[2]);
    float2 a1 = cadd(v[1], v[3]), a3 = csub(v[1], v[3]);
    a3 = make_float2(a3.y, -a3.x);
    out[FPAD(j)]        = cadd(a0, a1);
    out[FPAD(j + 512)]  = cadd(a2, a3);
    out[FPAD(j + 1024)] = csub(a0, a1);
    out[FPAD(j + 1536)] = csub(a2, a3);
}

__device__ __forceinline__ void fft2048s(float2 *bA, float2 *bB, int tid) {
    step8s<1>(bA, bB, tid);   __syncthreads();
    step8s<8>(bB, bA, tid);   __syncthreads();
    step8s<64>(bA, bB, tid);  __syncthreads();
    step4_512(bB, bA, tid);
    step4_512(bB, bA, tid + 256);
    __syncthreads();
}

__device__ __forceinline__ void spectral_H(const float2 *bA, float alpha, float2 *H, int tid) {
#pragma unroll
    for (int i = 0; i < 8; i++) {
        int k  = tid + (i << 8);
        int km = (2048 - k) & 2047;
        float2 Z  = bA[FPAD(k)];
        float2 Zm = bA[FPAD(km)];
        float qr = 0.5f * (Z.x + Zm.x);
        float qi = 0.5f * (Z.y - Zm.y);
        float rr = 0.5f * (Z.y + Zm.y);
        float ri = 0.5f * (Zm.x - Z.x);
        float mq = sqrtf(qr * qr + qi * qi);
        float mr = sqrtf(rr * rr + ri * ri);
        float pq = alpha * atanf(__logf(mq + 1e-8f));
        float pr = alpha * atanf(__logf(mr + 1e-8f));
        float cw = __cosf(pq - pr);
        H[i] = make_float2((qr * rr + qi * ri) * cw, (qi * rr - qr * ri) * cw);
    }
}

__global__ __launch_bounds__(256) void fft_cross_kernel(const float *__restrict__ alpha_l) {
    __shared__ float2 bA[2304];
    __shared__ float2 bB[2304];
    const int tid = threadIdx.x;
    const int c0  = blockIdx.x * 2;
    const int c1  = c0 + 1;
    const int b   = blockIdx.y;
    const float al0 = alpha_l[c0 & (PQD - 1)];
    const float al1 = alpha_l[c1 & (PQD - 1)];
    const size_t r0 = ((size_t)(b * PD + c0)) * PT;
    const size_t r1 = ((size_t)(b * PD + c1)) * PT;

    float2 H1[8], H2[8];

#pragma unroll
    for (int i = 0; i < 8; i++) {
        int t = tid + (i << 8);
        bA[FPAD(t)] = make_float2(g_qt[r0 + t], g_rt[r0 + t]);
    }
    __syncthreads();
    fft2048s(bA, bB, tid);
    spectral_H(bA, al0, H1, tid);
    __syncthreads();

#pragma unroll
    for (int i = 0; i < 8; i++) {
        int t = tid + (i << 8);
        bA[FPAD(t)] = make_float2(g_qt[r1 + t], g_rt[r1 + t]);
    }
    __syncthreads();
    fft2048s(bA, bB, tid);
    spectral_H(bA, al1, H2, tid);
    __syncthreads();

#pragma unroll
    for (int i = 0; i < 8; i++) {
        int k = tid + (i << 8);
        bA[FPAD(k)] = make_float2(H1[i].x - H2[i].y, -(H1[i].y + H2[i].x));
    }
    __syncthreads();
    fft2048s(bA, bB, tid);
    const float s = 1.0f / 2048.0f;
#pragma unroll
    for (int i = 0; i < 8; i++) {
        int t = tid + (i << 8);
        float2 F = bA[FPAD(t)];
        g_qt[r0 + t] = F.x * s;
        g_qt[r1 + t] = -F.y * s;
    }
}

// ---------------- fused hamilton + LN + gate + rot + residual + LN ------------
__global__ __launch_bounds__(256) void ham_ln_kernel(const float *__restrict__ spw,
                                                     const float *__restrict__ spb,
                                                     const float *__restrict__ gate,
                                                     const float *__restrict__ rot,
                                                     const float *__restrict__ ow,
                                                     const float *__restrict__ ob) {
    __shared__ float red[64];
    const int row = blockIdx.x;
    const size_t base = (size_t)row * PD;
    const int d = threadIdx.x;

    float i0 = g_r[base + d],       i1 = g_r[base + 256 + d];
    float i2 = g_r[base + 512 + d], i3 = g_r[base + 768 + d];
    float h0 = g_h[base + d],       h1 = g_h[base + 256 + d];
    float h2 = g_h[base + 512 + d], h3 = g_h[base + 768 + d];

    float qw = i0 * h0 - i1 * h1 - i2 * h2 - i3 * h3;
    float qx = i0 * h1 + i1 * h0 + i2 * h3 - i3 * h2;
    float qy = i0 * h2 - i1 * h3 + i2 * h0 + i3 * h1;
    float qz = i0 * h3 + i1 * h2 - i2 * h1 + i3 * h0;

    float s1 = qw + qx + qy + qz;
    float s2 = qw * qw + qx * qx + qy * qy + qz * qz;
    block_reduce2(s1, s2, red);
    float mean = s1 * (1.f / 1024.f);
    float var  = s2 * (1.f / 1024.f) - mean * mean;
    float inv  = rsqrtf(var + 1e-5f);
    float t0 = (qw - mean) * inv * spw[d]       + spb[d];
    float t1 = (qx - mean) * inv * spw[256 + d] + spb[256 + d];
    float t2 = (qy - mean) * inv * spw[512 + d] + spb[512 + d];
    float t3 = (qz - mean) * inv * spw[768 + d] + spb[768 + d];

    float g = gate[d];
    float f0 = t0 * g, f1 = t1 * g, f2 = t2 * g, f3 = t3 * g;
    float x0 = rot[0]  * f0 + rot[1]  * f1 + rot[2]  * f2 + rot[3]  * f3;
    float x1 = rot[4]  * f0 + rot[5]  * f1 + rot[6]  * f2 + rot[7]  * f3;
    float x2 = rot[8]  * f0 + rot[9]  * f1 + rot[10] * f2 + rot[11] * f3;
    float x3 = rot[12] * f0 + rot[13] * f1 + rot[14] * f2 + rot[15] * f3;

    x0 += g_x[base + d];
    x1 += g_x[base + 256 + d];
    x2 += g_x[base + 512 + d];
    x3 += g_x[base + 768 + d];
    s1 = x0 + x1 + x2 + x3;
    s2 = x0 * x0 + x1 * x1 + x2 * x2 + x3 * x3;
    block_reduce2(s1, s2, red);
    mean = s1 * (1.f / 1024.f);
    var  = s2 * (1.f / 1024.f) - mean * mean;
    inv  = rsqrtf(var + 1e-5f);
    float y0 = (x0 - mean) * inv * ow[d]       + ob[d];
    float y1 = (x1 - mean) * inv * ow[256 + d] + ob[256 + d];
    float y2 = (x2 - mean) * inv * ow[512 + d] + ob[512 + d];
    float y3 = (x3 - mean) * inv * ow[768 + d] + ob[768 + d];
    g_x[base + d]       = y0;
    g_x[base + 256 + d] = y1;
    g_x[base + 512 + d] = y2;
    g_x[base + 768 + d] = y3;
    split_store(base + d,       y0);
    split_store(base + 256 + d, y1);
    split_store(base + 512 + d, y2);
    split_store(base + 768 + d, y3);
}

// ---------------- pooling + cls LN -------------------------------------------
__global__ __launch_bounds__(1024) void pool_partial_kernel() {
    int b = blockIdx.y, ch = blockIdx.x, c = threadIdx.x;
    float s = 0.f;
    size_t base = ((size_t)b * PT + ch * 128) * PD + c;
    for (int t = 0; t < 128; t++) s += g_x[base + (size_t)t * PD];
    g_partial[(b * 16 + ch) * PD + c] = s;
}

__global__ __launch_bounds__(1024) void pool_finish_kernel(const float *__restrict__ clw,
                                                           const float *__restrict__ clb) {
    __shared__ float red[64];
    int b = blockIdx.x, c = threadIdx.x;
    float s = 0.f;
    for (int ch = 0; ch < 16; ch++) s += g_partial[(b * 16 + ch) * PD + c];
    float v = s * (1.f / (float)PT);
    float s1 = v, s2 = v * v;
    block_reduce2(s1, s2, red);
    float mean = s1 * (1.f / 1024.f);
    float var  = s2 * (1.f / 1024.f) - mean * mean;
    float inv  = rsqrtf(var + 1e-5f);
    g_hbuf[b * PD + c] = (v - mean) * inv * clw[c] + clb[c];
}

__global__ __launch_bounds__(128) void cls_kernel(const float *__restrict__ cW,
                                                  const float *__restrict__ cb,
                                                  float *__restrict__ out) {
    int n = blockIdx.x, b = blockIdx.y, tid = threadIdx.x;
    float s = 0.f;
    for (int c = tid; c < PD; c += 128) s += g_hbuf[b * PD + c] * cW[(size_t)n * PD + c];
#pragma unroll
    for (int o = 16; o > 0; o >>= 1) s += __shfl_xor_sync(0xffffffffu, s, o);
    __shared__ float sr[4];
    if ((tid & 31) == 0) sr[tid >> 5] = s;
    __syncthreads();
    if (tid == 0) out[b * NCLS + n] = sr[0] + sr[1] + sr[2] + sr[3] + cb[n];
}

// ---------------- host ---------------------------------------------------------
extern "C" void kernel_launch(void *const *d_in, const int *in_sizes, int n_in,
                              void *d_out, int out_size) {
    (void)in_sizes; (void)n_in; (void)out_size;
    const int   *tokens = (const int *)d_in[0];
    const float *embed  = (const float *)d_in[1];
    const float *pos    = (const float *)d_in[2];
    const float *Wq     = (const float *)d_in[3];
    const float *bq     = (const float *)d_in[4];
    const float *Wr     = (const float *)d_in[5];
    const float *br     = (const float *)d_in[6];
    const float *Wh     = (const float *)d_in[7];
    const float *bh     = (const float *)d_in[8];
    const float *alpha  = (const float *)d_in[9];
    const float *spw    = (const float *)d_in[10];
    const float *spb    = (const float *)d_in[11];
    const float *gate   = (const float *)d_in[12];
    const float *rot    = (const float *)d_in[13];
    const float *ow     = (const float *)d_in[14];
    const float *ob     = (const float *)d_in[15];
    const float *clw    = (const float *)d_in[16];
    const float *clb    = (const float *)d_in[17];
    const float *cW     = (const float *)d_in[18];
    const float *cb     = (const float *)d_in[19];
    float *out = (float *)d_out;

    cudaFuncSetAttribute(gemm_mma_kernel, cudaFuncAttributeMaxDynamicSharedMemorySize, SMEM_TOTAL);

    // side stream + fork/join events (host objects only; created per call,
    // never destroyed while capture is live — a handful of calls total)
    cudaStream_t s1;
    cudaStreamCreateWithFlags(&s1, cudaStreamNonBlocking);
    cudaEvent_t evF[PL + 1], evJ[PL + 1];
    for (int i = 0; i <= PL; i++) {
        cudaEventCreateWithFlags(&evF[i], cudaEventDisableTiming);
        cudaEventCreateWithFlags(&evJ[i], cudaEventDisableTiming);
    }

    // fork: convert_w on s1 concurrent with embed on main stream
    cudaEventRecord(evF[PL], 0);
    cudaStreamWaitEvent(s1, evF[PL], 0);
    convert_w_kernel<<<dim3(16384, 3), 256, 0, s1>>>(Wq, Wr, Wh);
    embed_kernel<<<NTOK, 256>>>(tokens, embed, pos);
    cudaEventRecord(evJ[PL], s1);
    cudaStreamWaitEvent(0, evJ[PL], 0);

    for (int l = 0; l < PL; l++) {
        // Q+R projections on main stream
        gemm_mma_kernel<<<dim3(8, 128, 2), 256, SMEM_TOTAL>>>(l, 0, bq + l * PD, br + l * PD, bh + l * PD);
        // fork: H projection on s1, concurrent with fft + transpose
        cudaEventRecord(evF[l], 0);
        cudaStreamWaitEvent(s1, evF[l], 0);
        gemm_mma_kernel<<<dim3(8, 128, 1), 256, SMEM_TOTAL, s1>>>(l, 2, bq + l * PD, br + l * PD, bh + l * PD);
        fft_cross_kernel<<<dim3(PD / 2, PB), 256>>>(alpha + l * PQD);
        transpose_back_kernel<<<dim3(64, 32, PB), dim3(32, 8)>>>();
        // join before hamilton
        cudaEventRecord(evJ[l], s1);
        cudaStreamWaitEvent(0, evJ[l], 0);
        ham_ln_kernel<<<NTOK, 256>>>(spw + l * PD, spb + l * PD,
                                     gate + l * PQD, rot + l * 16,
                                     ow + l * PD, ob + l * PD);
    }

    pool_partial_kernel<<<dim3(16, PB), 1024>>>();
    pool_finish_kernel<<<PB, 1024>>>(clw, clb);
    cls_kernel<<<dim3(NCLS, PB), 128>>>(cW, cb, out);
}

// round 12
// speedup vs baseline: 1.1487x; 1.0236x over previous
#include <cuda_runtime.h>
#include <cuda_bf16.h>
#include <cstdint>

// Problem constants
#define PB 8
#define PT 2048
#define PD 1024
#define PL 4
#define PQD 256
#define NCLS 1000
#define NTOK (PB*PT)           // 16384 rows
#define NEL  ((size_t)NTOK*PD) // 16,777,216

// ---------------- scratch (device globals; no allocation allowed) -------------
__device__ float g_x [NEL];    // activations / residual (fp32)
__device__ float g_h [NEL];    // H projection
__device__ float g_qt[NEL];    // Q transposed (b,c,t); reused for inter_t
__device__ float g_rt[NEL];    // R transposed
__device__ __nv_bfloat16 g_xh[NEL];             // bf16 split of g_x (hi)
__device__ __nv_bfloat16 g_xl[NEL];             // bf16 split of g_x (lo)
__device__ __nv_bfloat16 g_wbh[(size_t)12<<20]; // [z][l][n][k] bf16 hi
__device__ __nv_bfloat16 g_wbl[(size_t)12<<20]; // [z][l][n][k] bf16 lo
__device__ float g_partial[PB*16*PD];
__device__ float g_hbuf[PB*PD];

// ---------------- PTX helpers (baseline sm_80-class features only) ------------
__device__ __forceinline__ uint32_t smem_u32(const void *p) {
    uint32_t a;
    asm("{ .reg .u64 t; cvta.to.shared.u64 t, %1; cvt.u32.u64 %0, t; }" : "=r"(a) : "l"(p));
    return a;
}
__device__ __forceinline__ void cp16(uint32_t s, const void *g) {
    asm volatile("cp.async.cg.shared.global [%0], [%1], 16;" :: "r"(s), "l"(g));
}
__device__ __forceinline__ void cp_commit() {
    asm volatile("cp.async.commit_group;" ::: "memory");
}
template <int N> __device__ __forceinline__ void cp_wait() {
    asm volatile("cp.async.wait_group %0;" :: "n"(N) : "memory");
}
__device__ __forceinline__ void ldm_x4(uint32_t *r, uint32_t a) {
    asm volatile("ldmatrix.sync.aligned.m8n8.x4.shared.b16 {%0,%1,%2,%3}, [%4];"
                 : "=r"(r[0]), "=r"(r[1]), "=r"(r[2]), "=r"(r[3]) : "r"(a));
}
__device__ __forceinline__ void mma16816(float *d, const uint32_t *a, const uint32_t *b) {
    asm volatile(
        "mma.sync.aligned.m16n8k16.row.col.f32.bf16.bf16.f32 "
        "{%0,%1,%2,%3}, {%4,%5,%6,%7}, {%8,%9}, {%0,%1,%2,%3};"
        : "+f"(d[0]), "+f"(d[1]), "+f"(d[2]), "+f"(d[3])
        : "r"(a[0]), "r"(a[1]), "r"(a[2]), "r"(a[3]), "r"(b[0]), "r"(b[1]));
}

// dynamic smem: 2 buffers x (A 16KB + B 16KB) = 64KB  (R7 proven config)
#define BUF_BYTES 32768
#define SMEM_TOTAL 65536

// fused ham_ln smem: 32 x 1025 floats
#define HAM_SMEM (32*1025*4)

// ---------------- block reduce helper ----------------------------------------
__device__ __forceinline__ void block_reduce2(float &s1, float &s2, float *red) {
#pragma unroll
    for (int o = 16; o > 0; o >>= 1) {
        s1 += __shfl_xor_sync(0xffffffffu, s1, o);
        s2 += __shfl_xor_sync(0xffffffffu, s2, o);
    }
    int w = threadIdx.x >> 5, lane = threadIdx.x & 31;
    __syncthreads();
    if (lane == 0) { red[w] = s1; red[32 + w] = s2; }
    __syncthreads();
    int nw = blockDim.x >> 5;
    float a = 0.f, b = 0.f;
    for (int i = 0; i < nw; i++) { a += red[i]; b += red[32 + i]; }
    s1 = a; s2 = b;
}

__device__ __forceinline__ void split_store(size_t idx, float v) {
    __nv_bfloat16 h = __float2bfloat16(v);
    g_xh[idx] = h;
    g_xl[idx] = __float2bfloat16(v - __bfloat162float(h));
}

// ---------------- weight split (all 12 matrices, once per launch) -------------
__global__ __launch_bounds__(256) void convert_w_kernel(const float *__restrict__ Wq,
                                                        const float *__restrict__ Wr,
                                                        const float *__restrict__ Wh) {
    size_t i = (size_t)blockIdx.x * 256 + threadIdx.x;   // 0 .. 4M-1
    int z = blockIdx.y;
    const float *src = (z == 0) ? Wq : (z == 1) ? Wr : Wh;
    float v = src[i];
    __nv_bfloat16 h = __float2bfloat16(v);
    size_t o = ((size_t)z << 22) + i;
    g_wbh[o] = h;
    g_wbl[o] = __float2bfloat16(v - __bfloat162float(h));
}

// ---------------- embedding (+ bf16 split) ------------------------------------
__global__ __launch_bounds__(256) void embed_kernel(const int *__restrict__ tokens,
                                                    const float *__restrict__ embed,
                                                    const float *__restrict__ pos) {
    int row = blockIdx.x;
    int t   = row & (PT - 1);
    int tok = tokens[row];
    int c   = threadIdx.x * 4;
    float4 e = *(const float4 *)(embed + (size_t)tok * PD + c);
    float4 p = *(const float4 *)(pos + (size_t)t * PD + c);
    float4 y = make_float4(e.x + p.x, e.y + p.y, e.z + p.z, e.w + p.w);
    size_t base = (size_t)row * PD + c;
    *(float4 *)(g_x + base) = y;
    split_store(base + 0, y.x); split_store(base + 1, y.y);
    split_store(base + 2, y.z); split_store(base + 3, y.w);
}

// ---------------- mma.sync bf16x3 GEMM (128x128 tile, 2-stage; R7 config) -----
__device__ __forceinline__ void load_chunk_mma(int c, int bm, int bn,
                                               const __nv_bfloat16 *Wh_,
                                               const __nv_bfloat16 *Wl_,
                                               uint32_t buf, int tid) {
    int p  = c >> 4;
    int k0 = (c & 15) << 6;
    const __nv_bfloat16 *A  = (p < 2) ? g_xh : g_xl;
    const __nv_bfloat16 *Bw = (p == 1) ? Wl_ : Wh_;
#pragma unroll
    for (int i = 0; i < 4; i++) {            // A: 128 rows x 128B = 16KB
        int idx = tid + (i << 8);
        int r = idx >> 3, cc = idx & 7;
        const void *g = A + (size_t)(bm + r) * PD + k0 + cc * 8;
        cp16(buf + r * 128 + ((cc ^ (r & 7)) << 4), g);
    }
#pragma unroll
    for (int i = 0; i < 4; i++) {            // B: 128 rows x 128B = 16KB
        int idx = tid + (i << 8);
        int r = idx >> 3, cc = idx & 7;
        const void *g = Bw + (size_t)(bn + r) * PD + k0 + cc * 8;
        cp16(buf + 16384 + r * 128 + ((cc ^ (r & 7)) << 4), g);
    }
    cp_commit();
}

__global__ __launch_bounds__(256) void gemm_mma_kernel(int l, int zbase,
                                                       const float *__restrict__ bq,
                                                       const float *__restrict__ br,
                                                       const float *__restrict__ bh) {
    extern __shared__ char smem[];
    const int tid  = threadIdx.x;
    const int lane = tid & 31;
    const int wid  = tid >> 5;
    const int wm   = wid & 1;        // 2 warps in M
    const int wn   = wid >> 1;       // 4 warps in N
    const int z    = zbase + blockIdx.z;
    const int bn   = blockIdx.x * 128;
    const int bm   = blockIdx.y * 128;
    const uint32_t sb = smem_u32(smem);

    const size_t woff = ((size_t)(z * PL + l)) << 20;
    const __nv_bfloat16 *Wh_ = g_wbh + woff;
    const __nv_bfloat16 *Wl_ = g_wbl + woff;

    float acc[4][4][4];
#pragma unroll
    for (int i = 0; i < 4; i++)
#pragma unroll
        for (int j = 0; j < 4; j++)
#pragma unroll
            for (int k = 0; k < 4; k++) acc[i][j][k] = 0.f;

    const int aRow  = wm * 64 + (lane & 15);
    const int aHalf = lane >> 4;
    const int aSw   = aRow & 7;
    const int bRow  = wn * 32 + (lane & 7) + ((lane >> 4) << 3);
    const int bHalf = (lane >> 3) & 1;
    const int bSw   = bRow & 7;

    load_chunk_mma(0, bm, bn, Wh_, Wl_, sb, tid);

#pragma unroll 1
    for (int c = 0; c < 48; c++) {
        const uint32_t Ab = sb + (uint32_t)(c & 1) * BUF_BYTES;
        const uint32_t Bb = Ab + 16384;
        if (c + 1 < 48) {
            load_chunk_mma(c + 1, bm, bn, Wh_, Wl_,
                           sb + (uint32_t)((c + 1) & 1) * BUF_BYTES, tid);
            cp_wait<1>();
        } else {
            cp_wait<0>();
        }
        __syncthreads();

#pragma unroll
        for (int ks = 0; ks < 4; ks++) {
            uint32_t a[4][4];
#pragma unroll
            for (int im = 0; im < 4; im++) {
                uint32_t addr = Ab + (uint32_t)(aRow + im * 16) * 128
                              + (uint32_t)(((ks * 2 + aHalf) ^ aSw) << 4);
                ldm_x4(a[im], addr);
            }
            uint32_t b[2][4];
#pragma unroll
            for (int np = 0; np < 2; np++) {
                uint32_t addr = Bb + (uint32_t)(bRow + np * 16) * 128
                              + (uint32_t)(((ks * 2 + bHalf) ^ bSw) << 4);
                ldm_x4(b[np], addr);
            }
#pragma unroll
            for (int im = 0; im < 4; im++)
#pragma unroll
                for (int jn = 0; jn < 4; jn++)
                    mma16816(acc[im][jn], a[im], &b[jn >> 1][(jn & 1) << 1]);
        }
        __syncthreads();
    }

    const float *bias = (z == 0) ? bq : (z == 1) ? br : bh;
    if (z == 2) {
#pragma unroll
        for (int im = 0; im < 4; im++) {
            int r0 = bm + wm * 64 + im * 16 + (lane >> 2);
#pragma unroll
            for (int jn = 0; jn < 4; jn++) {
                int c0 = bn + wn * 32 + jn * 8 + (lane & 3) * 2;
                float b0 = __ldg(bias + c0), b1 = __ldg(bias + c0 + 1);
                float2 v0 = make_float2(acc[im][jn][0] + b0, acc[im][jn][1] + b1);
                float2 v1 = make_float2(acc[im][jn][2] + b0, acc[im][jn][3] + b1);
                *(float2 *)(g_h + (size_t)r0 * PD + c0)       = v0;
                *(float2 *)(g_h + (size_t)(r0 + 8) * PD + c0) = v1;
            }
        }
    } else {
        float *outp = (z == 0) ? g_qt : g_rt;
#pragma unroll
        for (int im = 0; im < 4; im++) {
            int m0 = bm + wm * 64 + im * 16 + (lane >> 2);
            int b_  = m0 >> 11;
            int t0  = m0 & (PT - 1);
            float *ob = outp + ((size_t)b_ << 21);
#pragma unroll
            for (int jn = 0; jn < 4; jn++) {
                int c0 = bn + wn * 32 + jn * 8 + (lane & 3) * 2;
                float b0 = __ldg(bias + c0), b1 = __ldg(bias + c0 + 1);
                ob[(size_t)c0 * PT + t0]           = acc[im][jn][0] + b0;
                ob[(size_t)(c0 + 1) * PT + t0]     = acc[im][jn][1] + b1;
                ob[(size_t)c0 * PT + t0 + 8]       = acc[im][jn][2] + b0;
                ob[(size_t)(c0 + 1) * PT + t0 + 8] = acc[im][jn][3] + b1;
            }
        }
    }
}

// ---------------- radix-8 Stockham FFT (2048-pt, 256 threads) -----------------
#define FPAD(i) ((i) + ((i) >> 3))

__device__ __forceinline__ float2 cmul(float2 a, float2 b) {
    return make_float2(a.x * b.x - a.y * b.y, a.x * b.y + a.y * b.x);
}
__device__ __forceinline__ float2 cadd(float2 a, float2 b) { return make_float2(a.x + b.x, a.y + b.y); }
__device__ __forceinline__ float2 csub(float2 a, float2 b) { return make_float2(a.x - b.x, a.y - b.y); }

__device__ __forceinline__ void dft8(float2 *v) {
    const float C = 0.70710678118654752f;
    float2 a0 = cadd(v[0], v[4]), a4 = csub(v[0], v[4]);
    float2 a1 = cadd(v[1], v[5]), a5 = csub(v[1], v[5]);
    float2 a2 = cadd(v[2], v[6]), a6 = csub(v[2], v[6]);
    float2 a3 = cadd(v[3], v[7]), a7 = csub(v[3], v[7]);
    a5 = make_float2(C * (a5.x + a5.y), C * (a5.y - a5.x));
    a6 = make_float2(a6.y, -a6.x);
    a7 = make_float2(C * (a7.y - a7.x), -C * (a7.x + a7.y));
    float2 b0 = cadd(a0, a2), b2 = csub(a0, a2);
    float2 b1 = cadd(a1, a3), b3 = csub(a1, a3);
    b3 = make_float2(b3.y, -b3.x);
    float2 b4 = cadd(a4, a6), b6 = csub(a4, a6);
    float2 b5 = cadd(a5, a7), b7 = csub(a5, a7);
    b7 = make_float2(b7.y, -b7.x);
    v[0] = cadd(b0, b1);  v[4] = csub(b0, b1);
    v[2] = cadd(b2, b3);  v[6] = csub(b2, b3);
    v[1] = cadd(b4, b5);  v[5] = csub(b4, b5);
    v[3] = cadd(b6, b7);  v[7] = csub(b6, b7);
}

template <int NS>
__device__ __forceinline__ void step8s(const float2 *in, float2 *out, int j) {
    float2 v[8];
#pragma unroll
    for (int r = 0; r < 8; r++) v[r] = in[FPAD(j + (r << 8))];
    if (NS > 1) {
        const int m = j & (NS - 1);
        float2 w1;
        __sincosf((float)m * (-6.283185307179586f / (NS * 8)), &w1.y, &w1.x);
        float2 w = w1;
#pragma unroll
        for (int r = 1; r < 8; r++) { v[r] = cmul(v[r], w); w = cmul(w, w1); }
    }
    dft8(v);
    const int m2 = j & (NS - 1);
    const int base = ((j - m2) << 3) + m2;
#pragma unroll
    for (int r = 0; r < 8; r++) out[FPAD(base + r * NS)] = v[r];
}

__device__ __forceinline__ void step4_512(const float2 *in, float2 *out, int j) {
    float2 v[4];
#pragma unroll
    for (int r = 0; r < 4; r++) v[r] = in[FPAD(j + (r << 9))];
    float2 w1;
    __sincosf((float)j * (-6.283185307179586f / 2048.f), &w1.y, &w1.x);
    v[1] = cmul(v[1], w1);
    float2 w2 = cmul(w1, w1);
    v[2] = cmul(v[2], w2);
    v[3] = cmul(v[3], cmul(w2, w1));
    float2 a0 = cadd(v[0], v[2]), a2 = csub(v[0], v[2]);
    float2 a1 = cadd(v[1], v[3]), a3 = csub(v[1], v[3]);
    a3 = make_float2(a3.y, -a3.x);
    out[FPAD(j)]        = cadd(a0, a1);
    out[FPAD(j + 512)]  = cadd(a2, a3);
    out[FPAD(j + 1024)] = csub(a0, a1);
    out[FPAD(j + 1536)] = csub(a2, a3);
}

__device__ __forceinline__ void fft2048s(float2 *bA, float2 *bB, int tid) {
    step8s<1>(bA, bB, tid);   __syncthreads();
    step8s<8>(bB, bA, tid);   __syncthreads();
    step8s<64>(bA, bB, tid);  __syncthreads();
    step4_512(bB, bA, tid);
    step4_512(bB, bA, tid + 256);
    __syncthreads();
}

__device__ __forceinline__ void spectral_H(const float2 *bA, float alpha, float2 *H, int tid) {
#pragma unroll
    for (int i = 0; i < 8; i++) {
        int k  = tid + (i << 8);
        int km = (2048 - k) & 2047;
        float2 Z  = bA[FPAD(k)];
        float2 Zm = bA[FPAD(km)];
        float qr = 0.5f * (Z.x + Zm.x);
        float qi = 0.5f * (Z.y - Zm.y);
        float rr = 0.5f * (Z.y + Zm.y);
        float ri = 0.5f * (Zm.x - Z.x);
        float mq = sqrtf(qr * qr + qi * qi);
        float mr = sqrtf(rr * rr + ri * ri);
        float pq = alpha * atanf(__logf(mq + 1e-8f));
        float pr = alpha * atanf(__logf(mr + 1e-8f));
        float cw = __cosf(pq - pr);
        H[i] = make_float2((qr * rr + qi * ri) * cw, (qi * rr - qr * ri) * cw);
    }
}

__global__ __launch_bounds__(256) void fft_cross_kernel(const float *__restrict__ alpha_l) {
    __shared__ float2 bA[2304];
    __shared__ float2 bB[2304];
    const int tid = threadIdx.x;
    const int c0  = blockIdx.x * 2;
    const int c1  = c0 + 1;
    const int b   = blockIdx.y;
    const float al0 = alpha_l[c0 & (PQD - 1)];
    const float al1 = alpha_l[c1 & (PQD - 1)];
    const size_t r0 = ((size_t)(b * PD + c0)) * PT;
    const size_t r1 = ((size_t)(b * PD + c1)) * PT;

    float2 H1[8], H2[8];

#pragma unroll
    for (int i = 0; i < 8; i++) {
        int t = tid + (i << 8);
        bA[FPAD(t)] = make_float2(g_qt[r0 + t], g_rt[r0 + t]);
    }
    __syncthreads();
    fft2048s(bA, bB, tid);
    spectral_H(bA, al0, H1, tid);
    __syncthreads();

#pragma unroll
    for (int i = 0; i < 8; i++) {
        int t = tid + (i << 8);
        bA[FPAD(t)] = make_float2(g_qt[r1 + t], g_rt[r1 + t]);
    }
    __syncthreads();
    fft2048s(bA, bB, tid);
    spectral_H(bA, al1, H2, tid);
    __syncthreads();

#pragma unroll
    for (int i = 0; i < 8; i++) {
        int k = tid + (i << 8);
        bA[FPAD(k)] = make_float2(H1[i].x - H2[i].y, -(H1[i].y + H2[i].x));
    }
    __syncthreads();
    fft2048s(bA, bB, tid);
    const float s = 1.0f / 2048.0f;
#pragma unroll
    for (int i = 0; i < 8; i++) {
        int t = tid + (i << 8);
        float2 F = bA[FPAD(t)];
        g_qt[r0 + t] = F.x * s;
        g_qt[r1 + t] = -F.y * s;
    }
}

// ------- fused transpose + hamilton + LN + gate + rot + residual + LN ---------
// Block: (t-tile of 32 tokens, batch b). Stages inter (from g_qt, c-major)
// through a padded smem tile, then per-warp token processing (warp = 4 tokens).
__global__ __launch_bounds__(256) void ham_ln_kernel(const float *__restrict__ spw,
                                                     const float *__restrict__ spb,
                                                     const float *__restrict__ gate,
                                                     const float *__restrict__ rot,
                                                     const float *__restrict__ ow,
                                                     const float *__restrict__ ob) {
    extern __shared__ float tile[];   // [32][1025]
    const int tid = threadIdx.x;
    const int b   = blockIdx.y;
    const int t0  = blockIdx.x * 32;
    const float *src = g_qt + ((size_t)b << 21);

    // load 32x1024 inter values: float4 along t, conflict-free smem scatter
#pragma unroll
    for (int i = 0; i < 32; i++) {
        int idx = tid + (i << 8);          // 0..8191 quads
        int c  = idx >> 3;
        int tq = (idx & 7) << 2;
        float4 v = *(const float4 *)(src + ((size_t)c << 11) + t0 + tq);
        tile[(tq + 0) * 1025 + c] = v.x;
        tile[(tq + 1) * 1025 + c] = v.y;
        tile[(tq + 2) * 1025 + c] = v.z;
        tile[(tq + 3) * 1025 + c] = v.w;
    }
    __syncthreads();

    const int wid = tid >> 5, lane = tid & 31;
    float rm[16];
#pragma unroll
    for (int i = 0; i < 16; i++) rm[i] = __ldg(rot + i);

#pragma unroll 1
    for (int tt = 0; tt < 4; tt++) {
        const int tl = wid * 4 + tt;
        const size_t base = ((size_t)((b << 11) + t0 + tl)) << 10;
        float q[4][8];
        float s1 = 0.f, s2 = 0.f;
#pragma unroll
        for (int k = 0; k < 8; k++) {
            int d = lane + (k << 5);
            float i0 = tile[tl * 1025 + d];
            float i1 = tile[tl * 1025 + 256 + d];
            float i2 = tile[tl * 1025 + 512 + d];
            float i3 = tile[tl * 1025 + 768 + d];
            float h0 = g_h[base + d];
            float h1 = g_h[base + 256 + d];
            float h2 = g_h[base + 512 + d];
            float h3 = g_h[base + 768 + d];
            float qw = i0 * h0 - i1 * h1 - i2 * h2 - i3 * h3;
            float qx = i0 * h1 + i1 * h0 + i2 * h3 - i3 * h2;
            float qy = i0 * h2 - i1 * h3 + i2 * h0 + i3 * h1;
            float qz = i0 * h3 + i1 * h2 - i2 * h1 + i3 * h0;
            q[0][k] = qw; q[1][k] = qx; q[2][k] = qy; q[3][k] = qz;
            s1 += qw + qx + qy + qz;
            s2 += qw * qw + qx * qx + qy * qy + qz * qz;
        }
#pragma unroll
        for (int o = 16; o > 0; o >>= 1) {
            s1 += __shfl_xor_sync(0xffffffffu, s1, o);
            s2 += __shfl_xor_sync(0xffffffffu, s2, o);
        }
        float mean = s1 * (1.f / 1024.f);
        float var  = s2 * (1.f / 1024.f) - mean * mean;
        float inv  = rsqrtf(var + 1e-5f);

        float xv[4][8];
        s1 = 0.f; s2 = 0.f;
#pragma unroll
        for (int k = 0; k < 8; k++) {
            int d = lane + (k << 5);
            float g = __ldg(gate + d);
            float f0 = ((q[0][k] - mean) * inv * __ldg(spw + d)       + __ldg(spb + d))       * g;
            float f1 = ((q[1][k] - mean) * inv * __ldg(spw + 256 + d) + __ldg(spb + 256 + d)) * g;
            float f2 = ((q[2][k] - mean) * inv * __ldg(spw + 512 + d) + __ldg(spb + 512 + d)) * g;
            float f3 = ((q[3][k] - mean) * inv * __ldg(spw + 768 + d) + __ldg(spb + 768 + d)) * g;
            float x0 = rm[0]  * f0 + rm[1]  * f1 + rm[2]  * f2 + rm[3]  * f3 + g_x[base + d];
            float x1 = rm[4]  * f0 + rm[5]  * f1 + rm[6]  * f2 + rm[7]  * f3 + g_x[base + 256 + d];
            float x2 = rm[8]  * f0 + rm[9]  * f1 + rm[10] * f2 + rm[11] * f3 + g_x[base + 512 + d];
            float x3 = rm[12] * f0 + rm[13] * f1 + rm[14] * f2 + rm[15] * f3 + g_x[base + 768 + d];
            xv[0][k] = x0; xv[1][k] = x1; xv[2][k] = x2; xv[3][k] = x3;
            s1 += x0 + x1 + x2 + x3;
            s2 += x0 * x0 + x1 * x1 + x2 * x2 + x3 * x3;
        }
#pragma unroll
        for (int o = 16; o > 0; o >>= 1) {
            s1 += __shfl_xor_sync(0xffffffffu, s1, o);
            s2 += __shfl_xor_sync(0xffffffffu, s2, o);
        }
        mean = s1 * (1.f / 1024.f);
        var  = s2 * (1.f / 1024.f) - mean * mean;
        inv  = rsqrtf(var + 1e-5f);
#pragma unroll
        for (int k = 0; k < 8; k++) {
            int d = lane + (k << 5);
#pragma unroll
            for (int j = 0; j < 4; j++) {
                int c = j * 256 + d;
                float y = (xv[j][k] - mean) * inv * __ldg(ow + c) + __ldg(ob + c);
                g_x[base + c] = y;
                split_store(base + c, y);
            }
        }
    }
}

// ---------------- pooling + cls LN -------------------------------------------
__global__ __launch_bounds__(1024) void pool_partial_kernel() {
    int b = blockIdx.y, ch = blockIdx.x, c = threadIdx.x;
    float s = 0.f;
    size_t base = ((size_t)b * PT + ch * 128) * PD + c;
    for (int t = 0; t < 128; t++) s += g_x[base + (size_t)t * PD];
    g_partial[(b * 16 + ch) * PD + c] = s;
}

__global__ __launch_bounds__(1024) void pool_finish_kernel(const float *__restrict__ clw,
                                                           const float *__restrict__ clb) {
    __shared__ float red[64];
    int b = blockIdx.x, c = threadIdx.x;
    float s = 0.f;
    for (int ch = 0; ch < 16; ch++) s += g_partial[(b * 16 + ch) * PD + c];
    float v = s * (1.f / (float)PT);
    float s1 = v, s2 = v * v;
    block_reduce2(s1, s2, red);
    float mean = s1 * (1.f / 1024.f);
    float var  = s2 * (1.f / 1024.f) - mean * mean;
    float inv  = rsqrtf(var + 1e-5f);
    g_hbuf[b * PD + c] = (v - mean) * inv * clw[c] + clb[c];
}

__global__ __launch_bounds__(128) void cls_kernel(const float *__restrict__ cW,
                                                  const float *__restrict__ cb,
                                                  float *__restrict__ out) {
    int n = blockIdx.x, b = blockIdx.y, tid = threadIdx.x;
    float s = 0.f;
    for (int c = tid; c < PD; c += 128) s += g_hbuf[b * PD + c] * cW[(size_t)n * PD + c];
#pragma unroll
    for (int o = 16; o > 0; o >>= 1) s += __shfl_xor_sync(0xffffffffu, s, o);
    __shared__ float sr[4];
    if ((tid & 31) == 0) sr[tid >> 5] = s;
    __syncthreads();
    if (tid == 0) out[b * NCLS + n] = sr[0] + sr[1] + sr[2] + sr[3] + cb[n];
}

// ---------------- host ---------------------------------------------------------
extern "C" void kernel_launch(void *const *d_in, const int *in_sizes, int n_in,
                              void *d_out, int out_size) {
    (void)in_sizes; (void)n_in; (void)out_size;
    const int   *tokens = (const int *)d_in[0];
    const float *embed  = (const float *)d_in[1];
    const float *pos    = (const float *)d_in[2];
    const float *Wq     = (const float *)d_in[3];
    const float *bq     = (const float *)d_in[4];
    const float *Wr     = (const float *)d_in[5];
    const float *br     = (const float *)d_in[6];
    const float *Wh     = (const float *)d_in[7];
    const float *bh     = (const float *)d_in[8];
    const float *alpha  = (const float *)d_in[9];
    const float *spw    = (const float *)d_in[10];
    const float *spb    = (const float *)d_in[11];
    const float *gate   = (const float *)d_in[12];
    const float *rot    = (const float *)d_in[13];
    const float *ow     = (const float *)d_in[14];
    const float *ob     = (const float *)d_in[15];
    const float *clw    = (const float *)d_in[16];
    const float *clb    = (const float *)d_in[17];
    const float *cW     = (const float *)d_in[18];
    const float *cb     = (const float *)d_in[19];
    float *out = (float *)d_out;

    cudaFuncSetAttribute(gemm_mma_kernel, cudaFuncAttributeMaxDynamicSharedMemorySize, SMEM_TOTAL);
    cudaFuncSetAttribute(ham_ln_kernel, cudaFuncAttributeMaxDynamicSharedMemorySize, HAM_SMEM);

    // side stream + fork/join events (host objects only)
    cudaStream_t s1;
    cudaStreamCreateWithFlags(&s1, cudaStreamNonBlocking);
    cudaEvent_t evF[PL + 1], evJ[PL + 1];
    for (int i = 0; i <= PL; i++) {
        cudaEventCreateWithFlags(&evF[i], cudaEventDisableTiming);
        cudaEventCreateWithFlags(&evJ[i], cudaEventDisableTiming);
    }

    // fork: convert_w on s1 concurrent with embed on main stream
    cudaEventRecord(evF[PL], 0);
    cudaStreamWaitEvent(s1, evF[PL], 0);
    convert_w_kernel<<<dim3(16384, 3), 256, 0, s1>>>(Wq, Wr, Wh);
    embed_kernel<<<NTOK, 256>>>(tokens, embed, pos);
    cudaEventRecord(evJ[PL], s1);
    cudaStreamWaitEvent(0, evJ[PL], 0);

    for (int l = 0; l < PL; l++) {
        // Q+R projections on main stream
        gemm_mma_kernel<<<dim3(8, 128, 2), 256, SMEM_TOTAL>>>(l, 0, bq + l * PD, br + l * PD, bh + l * PD);
        // fork: H projection on s1, concurrent with fft
        cudaEventRecord(evF[l], 0);
        cudaStreamWaitEvent(s1, evF[l], 0);
        gemm_mma_kernel<<<dim3(8, 128, 1), 256, SMEM_TOTAL, s1>>>(l, 2, bq + l * PD, br + l * PD, bh + l * PD);
        fft_cross_kernel<<<dim3(PD / 2, PB), 256>>>(alpha + l * PQD);
        // join before hamilton
        cudaEventRecord(evJ[l], s1);
        cudaStreamWaitEvent(0, evJ[l], 0);
        ham_ln_kernel<<<dim3(64, PB), 256, HAM_SMEM>>>(spw + l * PD, spb + l * PD,
                                                       gate + l * PQD, rot + l * 16,
                                                       ow + l * PD, ob + l * PD);
    }

    pool_partial_kernel<<<dim3(16, PB), 1024>>>();
    pool_finish_kernel<<<PB, 1024>>>(clw, clb);
    cls_kernel<<<dim3(NCLS, PB), 128>>>(cW, cb, out);
}